// round 2
// baseline (speedup 1.0000x reference)
#include <cuda_runtime.h>

// QuantumRegression: 12-wire state-vector sim, one block per batch sample.
// State (4096 complex64 = 32KB) lives in shared memory with an XOR-nibble
// swizzle; gates applied in fused 4-wire passes (16 register-resident amps
// per thread per pass). CNOTs are compile-time register permutations.
// Last-layer RZ is dropped (commutes to a diagonal before measurement).
// Final <Z_i> @ head_w reduction is fused into the last pass.

#define NW 12
#define NL 4

__device__ __forceinline__ int sw_idx(int a) { return a ^ ((a >> 4) & 0xF); }

// Fused gate (8 floats: G00r,G00i,G01r,G01i,G10r,G10i,G11r,G11i)
template<int M>
__device__ __forceinline__ void rot_full(float2* r, const float* __restrict__ g) {
    float g0 = g[0], g1 = g[1], g2 = g[2], g3 = g[3];
    float g4 = g[4], g5 = g[5], g6 = g[6], g7 = g[7];
#pragma unroll
    for (int k = 0; k < 16; k++) {
        if (!(k & M)) {
            float2 a0 = r[k], a1 = r[k | M];
            r[k].x     = g0 * a0.x - g1 * a0.y + g2 * a1.x - g3 * a1.y;
            r[k].y     = g0 * a0.y + g1 * a0.x + g2 * a1.y + g3 * a1.x;
            r[k | M].x = g4 * a0.x - g5 * a0.y + g6 * a1.x - g7 * a1.y;
            r[k | M].y = g4 * a0.y + g5 * a0.x + g6 * a1.y + g7 * a1.x;
        }
    }
}

template<int C, int T>
__device__ __forceinline__ void cnot(float2* r) {
#pragma unroll
    for (int k = 0; k < 16; k++) {
        if ((k & C) && !(k & T)) {
            float2 tmp = r[k]; r[k] = r[k | T]; r[k | T] = tmp;
        }
    }
}

__global__ void __launch_bounds__(256)
qsim_kernel(const float* __restrict__ inputs,
            const float* __restrict__ params,
            const float* __restrict__ head_w,
            const float* __restrict__ head_b,
            float* __restrict__ out)
{
    __shared__ float2 st[4096];            // 32 KB state vector (swizzled)
    __shared__ float  gates[NL][NW][8];    // fused RZ*RX (RX-only for last layer)
    __shared__ float  enc_c[NW], enc_s[NW], hw_s[NW];
    __shared__ float  red[8];

    const int b = blockIdx.x;
    const int t = threadIdx.x;

    // --- precompute gate matrices (shared across batch) ---
    // Single writer per slot: no races.
    if (t < NL * NW) {
        int l = t / NW;
        float th = params[t];
        float c, s;
        sincosf(0.5f * th, &s, &c);
        float* g = gates[l][t % NW];
        if (l == NL - 1) {
            // last layer: RZ dropped (diagonal commutes through CNOTs to
            // measurement) -> pure RX = [[c, -i s], [-i s, c]]
            g[0] = c;   g[1] = 0.f;
            g[2] = 0.f; g[3] = -s;
            g[4] = 0.f; g[5] = -s;
            g[6] = c;   g[7] = 0.f;
        } else {
            // G = RZ(th) * RX(th):
            // G00 = (c^2, -c s), G01 = (-s^2, -c s), G10 = (s^2, -c s), G11 = (c^2, c s)
            g[0] = c * c;  g[1] = -c * s;
            g[2] = -s * s; g[3] = -c * s;
            g[4] = s * s;  g[5] = -c * s;
            g[6] = c * c;  g[7] = c * s;
        }
    }
    if (t < NW) {
        float c, s;
        sincosf(0.5f * inputs[b * NW + t], &s, &c);
        enc_c[t] = c;
        enc_s[t] = s;
        hw_s[t] = head_w[t];
    }
    __syncthreads();

    // --- init: RY-encoded product state, amp[a] = prod_i (bit ? sin : cos) ---
    // ownership: a = (t<<4)|k ; t bit j <-> amp bit 4+j <-> wire 7-j ; k bit j <-> wire 11-j
    {
        float ph = 1.0f;
#pragma unroll
        for (int j = 0; j < 8; j++)
            ph *= ((t >> j) & 1) ? enc_s[7 - j] : enc_c[7 - j];
#pragma unroll
        for (int k = 0; k < 16; k++) {
            float q = ph;
#pragma unroll
            for (int j = 0; j < 4; j++)
                q *= ((k >> j) & 1) ? enc_s[11 - j] : enc_c[11 - j];
            st[sw_idx((t << 4) | k)] = make_float2(q, 0.0f);
        }
    }
    __syncthreads();

    float2 r[16];

#pragma unroll 1
    for (int l = 0; l < NL; l++) {
        const float* gl = &gates[l][0][0];

        // ---- Pass 0: wires 0..3 (amp bits 11..8), a = t | (k<<8)
        // local bit3<->wire0, bit2<->wire1, bit1<->wire2, bit0<->wire3
#pragma unroll
        for (int k = 0; k < 16; k++) r[k] = st[sw_idx(t | (k << 8))];
        rot_full<8>(r, gl + 0 * 8);
        rot_full<4>(r, gl + 1 * 8);
        rot_full<2>(r, gl + 2 * 8);
        rot_full<1>(r, gl + 3 * 8);
        cnot<8, 4>(r); cnot<4, 2>(r); cnot<2, 1>(r);
#pragma unroll
        for (int k = 0; k < 16; k++) st[sw_idx(t | (k << 8))] = r[k];
        __syncthreads();

        // ---- Pass 1: wires 3..6 (amp bits 8..5), a = (t&31) | ((t>>5)<<9) | (k<<5)
        // local bit3<->wire3 (already rotated), bit2<->wire4, bit1<->wire5, bit0<->wire6
        {
            int base = (t & 31) | ((t >> 5) << 9);
#pragma unroll
            for (int k = 0; k < 16; k++) r[k] = st[sw_idx(base | (k << 5))];
            rot_full<4>(r, gl + 4 * 8);
            rot_full<2>(r, gl + 5 * 8);
            rot_full<1>(r, gl + 6 * 8);
            cnot<8, 4>(r); cnot<4, 2>(r); cnot<2, 1>(r);
#pragma unroll
            for (int k = 0; k < 16; k++) st[sw_idx(base | (k << 5))] = r[k];
        }
        __syncthreads();

        // ---- Pass 2: wires 6..9 (amp bits 5..2), a = (t&3) | ((t>>2)<<6) | (k<<2)
        // local bit3<->wire6, bit2<->wire7, bit1<->wire8, bit0<->wire9
        {
            int base = (t & 3) | ((t >> 2) << 6);
#pragma unroll
            for (int k = 0; k < 16; k++) r[k] = st[sw_idx(base | (k << 2))];
            rot_full<4>(r, gl + 7 * 8);
            rot_full<2>(r, gl + 8 * 8);
            rot_full<1>(r, gl + 9 * 8);
            cnot<8, 4>(r); cnot<4, 2>(r); cnot<2, 1>(r);
#pragma unroll
            for (int k = 0; k < 16; k++) st[sw_idx(base | (k << 2))] = r[k];
        }
        __syncthreads();

        // ---- Pass 3: wires 8..11 (amp bits 3..0), a = (t<<4) | k
        // local bit3<->wire8, bit2<->wire9, bit1<->wire10, bit0<->wire11
#pragma unroll
        for (int k = 0; k < 16; k++) r[k] = st[sw_idx((t << 4) | k)];
        rot_full<2>(r, gl + 10 * 8);
        rot_full<1>(r, gl + 11 * 8);
        cnot<4, 2>(r); cnot<2, 1>(r);
        if (l < NL - 1) {
#pragma unroll
            for (int k = 0; k < 16; k++) st[sw_idx((t << 4) | k)] = r[k];
            __syncthreads();
        }
        // last layer: keep r[] in registers for the fused reduction
    }

    // --- fused measurement: out = sum_a |amp_a|^2 * c(a) + head_b
    // c(a) = sum_i hw[i] * (1 - 2*bit_{11-i}(a)); a = (t<<4)|k
    float whigh = 0.f;
#pragma unroll
    for (int j = 0; j < 8; j++) {
        float w = hw_s[7 - j];
        whigh += ((t >> j) & 1) ? -w : w;
    }
    float partial = 0.f;
#pragma unroll
    for (int k = 0; k < 16; k++) {
        float wl = whigh;
#pragma unroll
        for (int j = 0; j < 4; j++) {
            float w = hw_s[11 - j];
            wl += ((k >> j) & 1) ? -w : w;
        }
        partial += (r[k].x * r[k].x + r[k].y * r[k].y) * wl;
    }
#pragma unroll
    for (int o = 16; o; o >>= 1)
        partial += __shfl_xor_sync(0xFFFFFFFFu, partial, o);
    if ((t & 31) == 0) red[t >> 5] = partial;
    __syncthreads();
    if (t == 0) {
        float s = 0.f;
#pragma unroll
        for (int w = 0; w < 8; w++) s += red[w];
        out[b] = s + head_b[0];
    }
}

extern "C" void kernel_launch(void* const* d_in, const int* in_sizes, int n_in,
                              void* d_out, int out_size)
{
    const float* inputs = (const float*)d_in[0];
    const float* params = (const float*)d_in[1];
    const float* head_w = (const float*)d_in[2];
    const float* head_b = (const float*)d_in[3];
    float* out = (float*)d_out;

    int B = out_size;  // one block per sample
    qsim_kernel<<<B, 256>>>(inputs, params, head_w, head_b, out);
}

// round 3
// speedup vs baseline: 1.3124x; 1.3124x over previous
#include <cuda_runtime.h>

// QuantumRegression: 12-wire state-vector sim, TWO samples per block packed
// into f32x2 lanes (all gates are batch-shared, so every fma.rn.f32x2 does
// identical work for both samples). State = 4096 x (X=f32x2, Y=f32x2) = 64KB
// dynamic shared, XOR-nibble swizzled. Per layer: 4 passes, each rotating 3
// wires (local bits 2,1,0) with a free carry bit 3, so amps process as two
// independent 8-amp halves (32 amp regs). CNOTs are store-index permutations
// (tau tables) - zero instructions. RZ global phase dropped (|amp|^2
// measurement); last layer RZ dropped entirely. <Z>@head_w fused into the
// final pass.

typedef unsigned long long u64;

#define NW 12
#define NL 4

// ---- packed f32x2 helpers ----
static __device__ __forceinline__ u64 pack2(float lo, float hi) {
    u64 r; asm("mov.b64 %0, {%1, %2};" : "=l"(r) : "f"(lo), "f"(hi)); return r;
}
static __device__ __forceinline__ float2 unpack2(u64 v) {
    float2 r; asm("mov.b64 {%0, %1}, %2;" : "=f"(r.x), "=f"(r.y) : "l"(v)); return r;
}
static __device__ __forceinline__ u64 dup2(float v) { return pack2(v, v); }
static __device__ __forceinline__ u64 fma2(u64 a, u64 b, u64 c) {
    u64 d; asm("fma.rn.f32x2 %0, %1, %2, %3;" : "=l"(d) : "l"(a), "l"(b), "l"(c)); return d;
}
static __device__ __forceinline__ u64 mul2(u64 a, u64 b) {
    u64 d; asm("mul.rn.f32x2 %0, %1, %2;" : "=l"(d) : "l"(a), "l"(b)); return d;
}

__device__ __forceinline__ int sw_idx(int a) { return a ^ ((a >> 4) & 0xF); }

// ---- shared memory layout (dynamic) ----
#define SM_ST   0        // ulonglong2 st[4096]        : 65536
#define SM_GC   65536    // u64 gc[4*12*9]             : 3456
#define SM_ENC  68992    // u64 encC[12], encS[12]     : 192
#define SM_HW   69184    // float hw[12]               : 48
#define SM_WK   69232    // float wk[16]               : 64
#define SM_RED  69296    // float2 red[8]              : 64
#define SMEM_BYTES 69376

// Window mappings. Amp bit (11-i) <-> wire i. Local 4-bit k = (H<<3)|j,
// bit3 = free wire, bits 2,1,0 = rotated wires (3P, 3P+1, 3P+2).
// P0: free=w3,  rot w0,w1,w2  -> amp bits (8 | 11,10,9)
// P1: free=w2,  rot w3,w4,w5  -> amp bits (9 | 8,7,6)
// P2: free=w5,  rot w6,w7,w8  -> amp bits (6 | 5,4,3)
// P3: free=w8,  rot w9,w10,w11-> amp bits (3 | 2,1,0)
template<int P>
__device__ __forceinline__ int amp_addr(int t, int k) {
    int H = k >> 3, j = k & 7;
    if (P == 0)      return t | (j << 9) | (H << 8);
    else if (P == 1) return (t & 63) | ((t >> 6) << 10) | (j << 6) | (H << 9);
    else if (P == 2) return (t & 7)  | ((t >> 3) << 7)  | (j << 3) | (H << 6);
    else             return (t << 4) | k;
}

// Phase-folded gate: G = diag(1, e^{i th}) * RX(th), global phase dropped.
// row0: out0 = c*a0 - i s * a1 ; row1: general complex (A,B,C,D).
template<int M>
__device__ __forceinline__ void rot3(u64* X, u64* Y, const u64* __restrict__ g) {
    u64 c = g[0], s = g[1], ns = g[2];
    u64 A = g[3], B = g[4], nB = g[5], C = g[6], D = g[7], nD = g[8];
#pragma unroll
    for (int j = 0; j < 8; j++) if (!(j & M)) {
        u64 X0 = X[j], Y0 = Y[j], X1 = X[j|M], Y1 = Y[j|M];
        X[j]   = fma2(c, X0, mul2(s, Y1));
        Y[j]   = fma2(c, Y0, mul2(ns, X1));
        X[j|M] = fma2(D, Y1, fma2(C, X1, fma2(B, Y0, mul2(A, X0))));
        Y[j|M] = fma2(nD, X1, fma2(C, Y1, fma2(nB, X0, mul2(A, Y0))));
    }
}

// Pure RX (last layer, RZ commutes to measurement and is dropped).
template<int M>
__device__ __forceinline__ void rx3(u64* X, u64* Y, const u64* __restrict__ g) {
    u64 c = g[0], s = g[1], ns = g[2];
#pragma unroll
    for (int j = 0; j < 8; j++) if (!(j & M)) {
        u64 X0 = X[j], Y0 = Y[j], X1 = X[j|M], Y1 = Y[j|M];
        X[j]   = fma2(c, X0, mul2(s, Y1));
        Y[j]   = fma2(c, Y0, mul2(ns, X1));
        X[j|M] = fma2(c, X1, mul2(s, Y0));
        Y[j|M] = fma2(c, Y1, mul2(ns, X0));
    }
}

template<int P, bool LAST>
__device__ __forceinline__ void do_pass(ulonglong2* st, const u64* __restrict__ g,
                                        int t, float whigh, const float* __restrict__ wk,
                                        float* pacc)
{
    constexpr bool FINAL = LAST && (P == 3);
    // CNOT permutations (destination amp index for register slot j):
    // P0:  cnot<4,2>, cnot<2,1>          (cnots (0,1),(1,2))
    // P>=1: cnot<8,4>, cnot<4,2>, cnot<2,1>  (cnots (3P-1,3P),(3P,3P+1),(3P+1,3P+2))
    static constexpr int TAU0[8]  = {0,1,3,2,7,6,4,5};          // H=0 (bit3 clear: <8,4> inert)
    static constexpr int TAU1A[8] = {8,9,11,10,15,14,12,13};    // H=1, P==0
    static constexpr int TAU1B[8] = {15,14,12,13,8,9,11,10};    // H=1, P>=1

#pragma unroll 1
    for (int H = 0; H < 2; H++) {
        u64 X[8], Y[8];
#pragma unroll
        for (int j = 0; j < 8; j++) {
            ulonglong2 v = st[sw_idx(amp_addr<P>(t, (H << 3) | j))];
            X[j] = v.x; Y[j] = v.y;
        }
        if constexpr (LAST) {
            rx3<4>(X, Y, g);
            rx3<2>(X, Y, g + 9);
            rx3<1>(X, Y, g + 18);
        } else {
            rot3<4>(X, Y, g);
            rot3<2>(X, Y, g + 9);
            rot3<1>(X, Y, g + 18);
        }
        if constexpr (FINAL) {
#pragma unroll
            for (int j = 0; j < 8; j++) {
                int tau = H ? TAU1B[j] : TAU0[j];
                float wl = whigh + wk[tau];
                u64 U = fma2(X[j], X[j], mul2(Y[j], Y[j]));
                float2 u = unpack2(U);
                pacc[0] = fmaf(u.x, wl, pacc[0]);
                pacc[1] = fmaf(u.y, wl, pacc[1]);
            }
        } else {
#pragma unroll
            for (int j = 0; j < 8; j++) {
                int tau = H ? (P == 0 ? TAU1A[j] : TAU1B[j]) : TAU0[j];
                ulonglong2 v; v.x = X[j]; v.y = Y[j];
                st[sw_idx(amp_addr<P>(t, tau))] = v;
            }
        }
    }
}

__global__ void __launch_bounds__(256, 2)
qsim2_kernel(const float* __restrict__ inputs,
             const float* __restrict__ params,
             const float* __restrict__ head_w,
             const float* __restrict__ head_b,
             float* __restrict__ out)
{
    extern __shared__ char sm[];
    ulonglong2* st = (ulonglong2*)(sm + SM_ST);
    u64* gc    = (u64*)(sm + SM_GC);
    u64* encC  = (u64*)(sm + SM_ENC);
    u64* encS  = encC + NW;
    float* hw  = (float*)(sm + SM_HW);
    float* wk  = (float*)(sm + SM_WK);
    float2* red = (float2*)(sm + SM_RED);

    const int b = blockIdx.x;
    const int t = threadIdx.x;

    // --- gate precompute (single writer per slot) ---
    if (t < NL * NW) {
        int l = t / NW;
        float th = params[t];
        float c, s; sincosf(0.5f * th, &s, &c);
        u64* g = gc + t * 9;
        g[0] = dup2(c); g[1] = dup2(s); g[2] = dup2(-s);
        if (l < NL - 1) {
            float sn = 2.f * s * c;       // sin(th)
            float cs = c * c - s * s;     // cos(th)
            float A = s * sn, B = s * cs, C = c * cs, D = -c * sn;
            g[3] = dup2(A);  g[4] = dup2(B);  g[5] = dup2(-B);
            g[6] = dup2(C);  g[7] = dup2(D);  g[8] = dup2(-D);
        }
    }
    if (t < NW) {
        float c0, s0v, c1, s1v;
        sincosf(0.5f * inputs[(2 * b) * NW + t],     &s0v, &c0);
        sincosf(0.5f * inputs[(2 * b + 1) * NW + t], &s1v, &c1);
        encC[t] = pack2(c0, c1);
        encS[t] = pack2(s0v, s1v);
        hw[t] = head_w[t];
    }
    if (t < 16) {
        float w8 = head_w[8], w9 = head_w[9], w10 = head_w[10], w11 = head_w[11];
        wk[t] = ((t & 8) ? -w8 : w8) + ((t & 4) ? -w9 : w9)
              + ((t & 2) ? -w10 : w10) + ((t & 1) ? -w11 : w11);
    }
    __syncthreads();

    // measurement weight for amp bits 11..4 (owned via t in pass-3 layout)
    float whigh = 0.f;
#pragma unroll
    for (int m = 0; m < 8; m++) {
        float w = hw[7 - m];
        whigh += ((t >> m) & 1) ? -w : w;
    }

    // --- init: RY product state (both samples packed), pass-3 layout ---
    {
        u64 ph = dup2(1.0f);
#pragma unroll
        for (int m = 0; m < 8; m++)
            ph = mul2(ph, ((t >> m) & 1) ? encS[7 - m] : encC[7 - m]);
#pragma unroll
        for (int k = 0; k < 16; k++) {
            u64 q = ph;
            q = mul2(q, ((k >> 3) & 1) ? encS[8]  : encC[8]);
            q = mul2(q, ((k >> 2) & 1) ? encS[9]  : encC[9]);
            q = mul2(q, ((k >> 1) & 1) ? encS[10] : encC[10]);
            q = mul2(q, ( k       & 1) ? encS[11] : encC[11]);
            ulonglong2 v; v.x = q; v.y = 0ULL;
            st[sw_idx((t << 4) | k)] = v;
        }
    }
    __syncthreads();

    float pacc[2] = {0.f, 0.f};

#pragma unroll 1
    for (int l = 0; l < NL - 1; l++) {
        const u64* gl = gc + l * NW * 9;
        do_pass<0, false>(st, gl + 0 * 9, t, whigh, wk, pacc); __syncthreads();
        do_pass<1, false>(st, gl + 3 * 9, t, whigh, wk, pacc); __syncthreads();
        do_pass<2, false>(st, gl + 6 * 9, t, whigh, wk, pacc); __syncthreads();
        do_pass<3, false>(st, gl + 9 * 9, t, whigh, wk, pacc); __syncthreads();
    }
    {
        const u64* gl = gc + 3 * NW * 9;
        do_pass<0, true>(st, gl + 0 * 9, t, whigh, wk, pacc); __syncthreads();
        do_pass<1, true>(st, gl + 3 * 9, t, whigh, wk, pacc); __syncthreads();
        do_pass<2, true>(st, gl + 6 * 9, t, whigh, wk, pacc); __syncthreads();
        do_pass<3, true>(st, gl + 9 * 9, t, whigh, wk, pacc);  // fused measurement
    }

    // --- reduce both samples ---
    float p0 = pacc[0], p1 = pacc[1];
#pragma unroll
    for (int o = 16; o; o >>= 1) {
        p0 += __shfl_xor_sync(0xFFFFFFFFu, p0, o);
        p1 += __shfl_xor_sync(0xFFFFFFFFu, p1, o);
    }
    if ((t & 31) == 0) red[t >> 5] = make_float2(p0, p1);
    __syncthreads();
    if (t < 2) {
        float s = 0.f;
#pragma unroll
        for (int w = 0; w < 8; w++) s += (t == 0) ? red[w].x : red[w].y;
        out[2 * b + t] = s + head_b[0];
    }
}

extern "C" void kernel_launch(void* const* d_in, const int* in_sizes, int n_in,
                              void* d_out, int out_size)
{
    const float* inputs = (const float*)d_in[0];
    const float* params = (const float*)d_in[1];
    const float* head_w = (const float*)d_in[2];
    const float* head_b = (const float*)d_in[3];
    float* out = (float*)d_out;

    cudaFuncSetAttribute(qsim2_kernel, cudaFuncAttributeMaxDynamicSharedMemorySize, SMEM_BYTES);
    int B2 = out_size / 2;   // two samples per block
    qsim2_kernel<<<B2, 256, SMEM_BYTES>>>(inputs, params, head_w, head_b, out);
}

// round 5
// speedup vs baseline: 2.0057x; 1.5283x over previous
#include <cuda_runtime.h>

// QuantumRegression: 12-wire state-vector sim, two samples per block packed
// into f32x2 lanes. State = 4096 x ulonglong2 (X=f32x2, Y=f32x2) = 64KB in
// shared, storage index sw(e) = e ^ ((e>>4)&7) (conflict-free for all pass
// layouts at 16B granularity, and affine-in-k addressing per pass).
//
// Circuit restructure:
//  - Layer 0 (RY encode + RX*RZ + CNOT chain) folded into a closed-form
//    product-state init: amp(c) = prod_w v_w[c_w ^ c_{w-1}] (prefix parity).
//  - Layers 1..3: 3 passes of 4 rotated wires each (wires 0-3 / 4-7 / 8-11).
//    Boundary CNOT(3,4): control bit lives in t -> folded into pass-B store
//    base (conjugated through the in-window staircase: Stair(k^8c)).
//    Boundary CNOT(7,8): deferred into next pass-A load base. The deferred
//    perm must be conjugated by the already-applied staircase:
//    Stair o C78 o Stair^-1 = flip bits 3..0 iff bit4  (Stair(8)=0xF).
//  - RZ global phase dropped everywhere; last layer's RZs dropped entirely
//    (diagonal before |amp|^2 measurement). Last layer = pure RX.
//  - <Z> @ head_w measurement fused into the final pass (no store).

typedef unsigned long long u64;

#define NW 12

// ---- packed f32x2 helpers ----
static __device__ __forceinline__ u64 pack2(float lo, float hi) {
    u64 r; asm("mov.b64 %0, {%1, %2};" : "=l"(r) : "f"(lo), "f"(hi)); return r;
}
static __device__ __forceinline__ float2 unpack2(u64 v) {
    float2 r; asm("mov.b64 {%0, %1}, %2;" : "=f"(r.x), "=f"(r.y) : "l"(v)); return r;
}
static __device__ __forceinline__ u64 dup2(float v) { return pack2(v, v); }
static __device__ __forceinline__ u64 fma2(u64 a, u64 b, u64 c) {
    u64 d; asm("fma.rn.f32x2 %0, %1, %2, %3;" : "=l"(d) : "l"(a), "l"(b), "l"(c)); return d;
}
static __device__ __forceinline__ u64 mul2(u64 a, u64 b) {
    u64 d; asm("mul.rn.f32x2 %0, %1, %2;" : "=l"(d) : "l"(a), "l"(b)); return d;
}
static __device__ __forceinline__ u64 neg2(u64 a) { return a ^ 0x8000000080000000ULL; }

// staircase CNOT permutation on 4 bits (GF2-linear: tau(a^b)=tau(a)^tau(b))
__device__ __host__ __forceinline__ constexpr int tau4(int k) {
    int b3 = (k >> 3) & 1;
    int b2 = ((k >> 2) & 1) ^ b3;
    int b1 = ((k >> 1) & 1) ^ b2;
    int b0 = (k & 1) ^ b1;
    return (b3 << 3) | (b2 << 2) | (b1 << 1) | b0;
}

// ---- shared memory layout (bytes) ----
#define SM_ST   0        // ulonglong2 st[4096]            : 65536
#define SM_G    65536    // ulonglong2 gct[3*12*5]         : 2880  (layers 1..3)
#define SM_F    68416    // ulonglong2 F[16]               : 256
#define SM_V    68672    // ulonglong2 v[12][2]            : 384
#define SM_HW   69056    // float hw[12]                   : 48
#define SM_WK   69104    // float wk[16]                   : 64
#define SM_RED  69168    // float2 red[8]                  : 64
#define SMEM_BYTES 69232

// Fused phase-folded gate RZ*RX (global phase dropped):
// row0: out0 = c*a0 - i s*a1 ; row1: out1 = e^{i th}(-i s a0 + c a1)
template<int M>
__device__ __forceinline__ void rot1(u64* X, u64* Y, const ulonglong2* __restrict__ g) {
    ulonglong2 p0 = g[0], p1 = g[1], p2 = g[2], p3 = g[3], p4 = g[4];
    u64 c = p0.x, s = p0.y, ns = p1.x, A = p1.y;
    u64 B = p2.x, nB = p2.y, C = p3.x, D = p3.y, nD = p4.x;
#pragma unroll
    for (int j = 0; j < 16; j++) if (!(j & M)) {
        u64 X0 = X[j], Y0 = Y[j], X1 = X[j|M], Y1 = Y[j|M];
        X[j]   = fma2(c, X0, mul2(s, Y1));
        Y[j]   = fma2(c, Y0, mul2(ns, X1));
        X[j|M] = fma2(D, Y1, fma2(C, X1, fma2(B, Y0, mul2(A, X0))));
        Y[j|M] = fma2(nD, X1, fma2(C, Y1, fma2(nB, X0, mul2(A, Y0))));
    }
}

// Pure RX (last layer)
template<int M>
__device__ __forceinline__ void rx1(u64* X, u64* Y, const ulonglong2* __restrict__ g) {
    ulonglong2 p0 = g[0];
    u64 c = p0.x, s = p0.y, ns = g[1].x;
#pragma unroll
    for (int j = 0; j < 16; j++) if (!(j & M)) {
        u64 X0 = X[j], Y0 = Y[j], X1 = X[j|M], Y1 = Y[j|M];
        X[j]   = fma2(c, X0, mul2(s, Y1));
        Y[j]   = fma2(c, Y0, mul2(ns, X1));
        X[j|M] = fma2(c, X1, mul2(s, Y0));
        Y[j|M] = fma2(c, Y1, mul2(ns, X0));
    }
}

// Per-pass element address masks (applied to swizzled storage index).
template<int P>
__device__ __forceinline__ int addr_of(int base, int k) {
    if (P == 0)      return base + (k << 8);                  // immediate offsets
    else if (P == 1) return base ^ ((k << 4) | (k & 7));      // compile-time XOR mask
    else             return base ^ k;                         // compile-time XOR mask
}

// One pass: load 16 amps, 4 rotations, CNOT perm on store (or fused measure).
// MODE: 0 = rot (layers 1,2), 1 = rx (layer 3), 2 = rx + fused measurement.
template<int P, int MODE>
__device__ __forceinline__ void do_pass(ulonglong2* __restrict__ st,
                                        const ulonglong2* __restrict__ g,
                                        int loadBase, int storeBase,
                                        float whigh, const float* __restrict__ wk,
                                        int wkxor, float* pacc)
{
    u64 X[16], Y[16];
#pragma unroll
    for (int k = 0; k < 16; k++) {
        ulonglong2 v = st[addr_of<P>(loadBase, k)];
        X[k] = v.x; Y[k] = v.y;
    }
    if (MODE == 0) { rot1<8>(X, Y, g); rot1<4>(X, Y, g + 5); rot1<2>(X, Y, g + 10); rot1<1>(X, Y, g + 15); }
    else           { rx1<8>(X, Y, g);  rx1<4>(X, Y, g + 5);  rx1<2>(X, Y, g + 10);  rx1<1>(X, Y, g + 15);  }

    if (MODE == 2) {
#pragma unroll
        for (int k = 0; k < 16; k++) {
            int idx = tau4(k) ^ wkxor;   // C78-then-staircase folded into weight index
            float wl = whigh + wk[idx];
            u64 U = fma2(X[k], X[k], mul2(Y[k], Y[k]));
            float2 u = unpack2(U);
            pacc[0] = fmaf(u.x, wl, pacc[0]);
            pacc[1] = fmaf(u.y, wl, pacc[1]);
        }
    } else {
#pragma unroll
        for (int k = 0; k < 16; k++) {
            int tk = tau4(k);
            ulonglong2 v; v.x = X[k]; v.y = Y[k];
            st[addr_of<P>(storeBase, tk)] = v;
        }
    }
}

__global__ void __launch_bounds__(256, 2)
qsim3_kernel(const float* __restrict__ inputs,
             const float* __restrict__ params,
             const float* __restrict__ head_w,
             const float* __restrict__ head_b,
             float* __restrict__ out)
{
    extern __shared__ char sm[];
    ulonglong2* st   = (ulonglong2*)(sm + SM_ST);
    ulonglong2* gct  = (ulonglong2*)(sm + SM_G);
    ulonglong2* Ftab = (ulonglong2*)(sm + SM_F);
    ulonglong2* vtab = (ulonglong2*)(sm + SM_V);
    float* hw  = (float*)(sm + SM_HW);
    float* wk  = (float*)(sm + SM_WK);
    float2* red = (float2*)(sm + SM_RED);

    const int b = blockIdx.x;
    const int t = threadIdx.x;

    // ---- phase 1: gates (layers 1..3), layer-0 product vectors v, weights ----
    if (t < 36) {                      // layers 1..3, wire = t%12
        int l = 1 + t / NW, w = t % NW;
        float th = params[l * NW + w];
        float c, s; sincosf(0.5f * th, &s, &c);
        ulonglong2* g = gct + ((l - 1) * NW + w) * 5;
        u64 zc = dup2(c), zs = dup2(s);
        if (l < 3) {
            float sn = 2.f * s * c, cn = c * c - s * s;
            float A = s * sn, B = s * cn, C = c * cn, D = -c * sn;
            ulonglong2 e0; e0.x = zc;        e0.y = zs;        g[0] = e0;
            ulonglong2 e1; e1.x = dup2(-s);  e1.y = dup2(A);   g[1] = e1;
            ulonglong2 e2; e2.x = dup2(B);   e2.y = dup2(-B);  g[2] = e2;
            ulonglong2 e3; e3.x = dup2(C);   e3.y = dup2(D);   g[3] = e3;
            ulonglong2 e4; e4.x = dup2(-D);  e4.y = 0ULL;      g[4] = e4;
        } else {                        // last layer: pure RX
            ulonglong2 e0; e0.x = zc;        e0.y = zs;        g[0] = e0;
            ulonglong2 e1; e1.x = dup2(-s);  e1.y = 0ULL;      g[1] = e1;
        }
    }
    if (t < NW) {                      // layer-0 per-wire 2-vectors (both samples)
        int w = t;
        float th = params[w];
        float c0, s0; sincosf(0.5f * th, &s0, &c0);
        float cn = c0 * c0 - s0 * s0, sn = 2.f * s0 * c0;
        float v0x[2], v0y[2], v1x[2], v1y[2];
#pragma unroll
        for (int j = 0; j < 2; j++) {
            float cy, sy; sincosf(0.5f * inputs[(2 * b + j) * NW + w], &sy, &cy);
            v0x[j] = c0 * cy;  v0y[j] = -s0 * sy;
            float zx = c0 * sy, zy = -s0 * cy;           // z = -i s cy + c sy
            v1x[j] = cn * zx - sn * zy;                   // e^{i th} * z
            v1y[j] = sn * zx + cn * zy;
        }
        ulonglong2 e0; e0.x = pack2(v0x[0], v0x[1]); e0.y = pack2(v0y[0], v0y[1]);
        ulonglong2 e1; e1.x = pack2(v1x[0], v1x[1]); e1.y = pack2(v1y[0], v1y[1]);
        vtab[(w << 1) | 0] = e0;
        vtab[(w << 1) | 1] = e1;
        hw[w] = head_w[w];
    }
    if (t < 16) {                      // measurement weights for wires 8..11
        float w8 = head_w[8], w9 = head_w[9], w10 = head_w[10], w11 = head_w[11];
        wk[t] = ((t & 8) ? -w8 : w8) + ((t & 4) ? -w9 : w9)
              + ((t & 2) ? -w10 : w10) + ((t & 1) ? -w11 : w11);
    }
    __syncthreads();

    // ---- phase 2: F table (wires 0..3 staircase products, batch-shared) ----
    if (t < 16) {
        int c0 = (t >> 3) & 1, c1 = (t >> 2) & 1, c2 = (t >> 1) & 1, c3 = t & 1;
        int b0 = c0, b1 = c1 ^ c0, b2 = c2 ^ c1, b3 = c3 ^ c2;
        ulonglong2 a = vtab[0 | b0];
        u64 PX = a.x, PY = a.y;
        int bb[3] = {b1, b2, b3};
#pragma unroll
        for (int w = 1; w <= 3; w++) {
            ulonglong2 q = vtab[(w << 1) | bb[w - 1]];
            u64 nx = fma2(PX, q.x, neg2(mul2(PY, q.y)));
            u64 ny = fma2(PX, q.y, mul2(PY, q.x));
            PX = nx; PY = ny;
        }
        ulonglong2 f; f.x = PX; f.y = PY; Ftab[t] = f;
    }

    // per-thread bases (reused across layers)
    const int baseA  = t ^ ((t >> 4) & 7);              // pass-A canonical base
    // Deferred CNOT(7,8) conjugated through the already-applied staircase:
    // Stair o C78 o Stair^-1 flips bits 3..0 iff bit 4 (Stair(8) = 0xF).
    const int tA2    = t ^ (((t >> 4) & 1) * 0xF);
    const int baseA2 = tA2 ^ ((tA2 >> 4) & 7);          // pass-A load base (L2,L3)
    const int baseB  = ((t >> 4) << 8) | (t & 15);
    const int baseBs = baseB ^ (((t >> 4) & 1) ? 0xF7 : 0);  // CNOT(3,4) fold
    const int baseC  = (t << 4) | (t & 7);
    const int wkxor  = (t & 1) ? 0xF : 0;               // CNOT(7,8) fold at measure

    // measurement weight for wires 0..7 (t bits 7..0, wire i <-> t bit 7-i)
    float whigh = 0.f;
#pragma unroll
    for (int m = 0; m < 8; m++) {
        float w = hw[7 - m];
        whigh += ((t >> m) & 1) ? -w : w;
    }
    __syncthreads();

    float pacc[2] = {0.f, 0.f};
    const ulonglong2* g1 = gct;           // layer 1
    const ulonglong2* g2 = gct + 60;      // layer 2
    const ulonglong2* g3 = gct + 120;     // layer 3 (rx)

    // ======== Layer 1, pass A: closed-form init in registers + rot + store ====
    {
        u64 X[16], Y[16];
        int u = t ^ (t >> 1);             // u bit (11-w) = b_w for wires 5..11
        ulonglong2 p5 = vtab[(5 << 1) | ((u >> 6) & 1)];
        u64 PX = p5.x, PY = p5.y;
#pragma unroll
        for (int w = 6; w <= 11; w++) {
            ulonglong2 q = vtab[(w << 1) | ((u >> (11 - w)) & 1)];
            u64 nx = fma2(PX, q.x, neg2(mul2(PY, q.y)));
            u64 ny = fma2(PX, q.y, mul2(PY, q.x));
            PX = nx; PY = ny;
        }
        int t7 = (t >> 7) & 1;
        ulonglong2 q0 = vtab[(4 << 1) | t7];
        ulonglong2 q1 = vtab[(4 << 1) | (t7 ^ 1)];
        u64 R0X = fma2(PX, q0.x, neg2(mul2(PY, q0.y)));
        u64 R0Y = fma2(PX, q0.y, mul2(PY, q0.x));
        u64 R1X = fma2(PX, q1.x, neg2(mul2(PY, q1.y)));
        u64 R1Y = fma2(PX, q1.y, mul2(PY, q1.x));
#pragma unroll
        for (int k = 0; k < 16; k++) {
            ulonglong2 Fk = Ftab[k];
            u64 QX = (k & 1) ? R1X : R0X;
            u64 QY = (k & 1) ? R1Y : R0Y;
            X[k] = fma2(Fk.x, QX, neg2(mul2(Fk.y, QY)));
            Y[k] = fma2(Fk.x, QY, mul2(Fk.y, QX));
        }
        rot1<8>(X, Y, g1); rot1<4>(X, Y, g1 + 5); rot1<2>(X, Y, g1 + 10); rot1<1>(X, Y, g1 + 15);
#pragma unroll
        for (int k = 0; k < 16; k++) {
            int tk = tau4(k);
            ulonglong2 v; v.x = X[k]; v.y = Y[k];
            st[baseA + (tk << 8)] = v;
        }
    }
    __syncthreads();

    do_pass<1, 0>(st, g1 + 20, baseB, baseBs, whigh, wk, 0, pacc); __syncthreads();
    do_pass<2, 0>(st, g1 + 40, baseC, baseC,  whigh, wk, 0, pacc); __syncthreads();

    // ======== Layer 2 ========
    do_pass<0, 0>(st, g2,      baseA2, baseA, whigh, wk, 0, pacc); __syncthreads();
    do_pass<1, 0>(st, g2 + 20, baseB,  baseBs, whigh, wk, 0, pacc); __syncthreads();
    do_pass<2, 0>(st, g2 + 40, baseC,  baseC,  whigh, wk, 0, pacc); __syncthreads();

    // ======== Layer 3 (pure RX, fused measurement in pass C) ========
    do_pass<0, 1>(st, g3,      baseA2, baseA, whigh, wk, 0, pacc); __syncthreads();
    do_pass<1, 1>(st, g3 + 20, baseB,  baseBs, whigh, wk, 0, pacc); __syncthreads();
    do_pass<2, 2>(st, g3 + 40, baseC,  baseC,  whigh, wk, wkxor, pacc);

    // ---- reduce both samples ----
    float p0 = pacc[0], p1 = pacc[1];
#pragma unroll
    for (int o = 16; o; o >>= 1) {
        p0 += __shfl_xor_sync(0xFFFFFFFFu, p0, o);
        p1 += __shfl_xor_sync(0xFFFFFFFFu, p1, o);
    }
    if ((t & 31) == 0) red[t >> 5] = make_float2(p0, p1);
    __syncthreads();
    if (t < 2) {
        float s = 0.f;
#pragma unroll
        for (int w = 0; w < 8; w++) s += (t == 0) ? red[w].x : red[w].y;
        out[2 * b + t] = s + head_b[0];
    }
}

extern "C" void kernel_launch(void* const* d_in, const int* in_sizes, int n_in,
                              void* d_out, int out_size)
{
    const float* inputs = (const float*)d_in[0];
    const float* params = (const float*)d_in[1];
    const float* head_w = (const float*)d_in[2];
    const float* head_b = (const float*)d_in[3];
    float* out = (float*)d_out;

    cudaFuncSetAttribute(qsim3_kernel, cudaFuncAttributeMaxDynamicSharedMemorySize, SMEM_BYTES);
    int B2 = out_size / 2;   // two samples per block
    qsim3_kernel<<<B2, 256, SMEM_BYTES>>>(inputs, params, head_w, head_b, out);
}

// round 6
// speedup vs baseline: 2.0182x; 1.0062x over previous
#include <cuda_runtime.h>

// QuantumRegression: 12-wire state-vector sim, two samples per block packed
// into f32x2 lanes. State = 4096 x ulonglong2 (X=f32x2, Y=f32x2) = 64KB in
// shared, storage index sw(e) = e ^ ((e>>4)&7) (conflict-free for all pass
// layouts at 16B granularity, and affine-in-k addressing per pass).
//
// Circuit restructure (identical algebra to the verified R5 kernel):
//  - Layer 0 folded into closed-form product-state init (prefix parity).
//  - Layers 1..3: 3 passes of 4 rotated wires (0-3 / 4-7 / 8-11); boundary
//    CNOT(3,4) folded into pass-B store base, boundary CNOT(7,8) deferred
//    into next pass-A load base (conjugated: flip bits 3..0 iff bit4).
//  - RZ global phase dropped; last layer = pure RX; <Z>@head_w fused.
//
// This revision: software-pipelined passes. Loads are fused into the first
// rotation (rot<8> pairs (j, j|8) fire after only 2 loads), stores are fused
// into the last rotation (rot<1> pairs (j, j|1) store immediately), so LSU
// and FMA pipes overlap instead of alternating bursts.

typedef unsigned long long u64;

#define NW 12

// ---- packed f32x2 helpers ----
static __device__ __forceinline__ u64 pack2(float lo, float hi) {
    u64 r; asm("mov.b64 %0, {%1, %2};" : "=l"(r) : "f"(lo), "f"(hi)); return r;
}
static __device__ __forceinline__ float2 unpack2(u64 v) {
    float2 r; asm("mov.b64 {%0, %1}, %2;" : "=f"(r.x), "=f"(r.y) : "l"(v)); return r;
}
static __device__ __forceinline__ u64 dup2(float v) { return pack2(v, v); }
static __device__ __forceinline__ u64 fma2(u64 a, u64 b, u64 c) {
    u64 d; asm("fma.rn.f32x2 %0, %1, %2, %3;" : "=l"(d) : "l"(a), "l"(b), "l"(c)); return d;
}
static __device__ __forceinline__ u64 mul2(u64 a, u64 b) {
    u64 d; asm("mul.rn.f32x2 %0, %1, %2;" : "=l"(d) : "l"(a), "l"(b)); return d;
}
static __device__ __forceinline__ u64 neg2(u64 a) { return a ^ 0x8000000080000000ULL; }

// staircase CNOT permutation on 4 bits (GF2-linear)
__device__ __host__ __forceinline__ constexpr int tau4(int k) {
    int b3 = (k >> 3) & 1;
    int b2 = ((k >> 2) & 1) ^ b3;
    int b1 = ((k >> 1) & 1) ^ b2;
    int b0 = (k & 1) ^ b1;
    return (b3 << 3) | (b2 << 2) | (b1 << 1) | b0;
}

// ---- shared memory layout (bytes) ----
#define SM_ST   0        // ulonglong2 st[4096]            : 65536
#define SM_G    65536    // ulonglong2 gct[3*12*5]         : 2880
#define SM_F    68416    // ulonglong2 F[16]               : 256
#define SM_V    68672    // ulonglong2 v[12][2]            : 384
#define SM_HW   69056    // float hw[12]                   : 48
#define SM_WK   69104    // float wk[16]                   : 64
#define SM_RED  69168    // float2 red[8]                  : 64
#define SMEM_BYTES 69232

// ---- gate coefficient bundles (broadcast LDS, loaded once per rotation) ----
struct GR { u64 c, s, ns, A, B, nB, C, D, nD; };
static __device__ __forceinline__ GR load_gr(const ulonglong2* __restrict__ g) {
    GR r; ulonglong2 p0 = g[0], p1 = g[1], p2 = g[2], p3 = g[3], p4 = g[4];
    r.c = p0.x; r.s = p0.y; r.ns = p1.x; r.A = p1.y;
    r.B = p2.x; r.nB = p2.y; r.C = p3.x; r.D = p3.y; r.nD = p4.x;
    return r;
}
struct GX { u64 c, s, ns; };
static __device__ __forceinline__ GX load_gx(const ulonglong2* __restrict__ g) {
    GX r; ulonglong2 p0 = g[0]; r.c = p0.x; r.s = p0.y; r.ns = g[1].x; return r;
}

// one fused RZ*RX rotation on pair (i0, i1)
static __device__ __forceinline__ void rotp(const GR& G, u64* X, u64* Y, int i0, int i1) {
    u64 X0 = X[i0], Y0 = Y[i0], X1 = X[i1], Y1 = Y[i1];
    X[i0] = fma2(G.c, X0, mul2(G.s, Y1));
    Y[i0] = fma2(G.c, Y0, mul2(G.ns, X1));
    X[i1] = fma2(G.D, Y1, fma2(G.C, X1, fma2(G.B, Y0, mul2(G.A, X0))));
    Y[i1] = fma2(G.nD, X1, fma2(G.C, Y1, fma2(G.nB, X0, mul2(G.A, Y0))));
}
// one pure RX rotation on pair (i0, i1)
static __device__ __forceinline__ void rxp(const GX& G, u64* X, u64* Y, int i0, int i1) {
    u64 X0 = X[i0], Y0 = Y[i0], X1 = X[i1], Y1 = Y[i1];
    X[i0] = fma2(G.c, X0, mul2(G.s, Y1));
    Y[i0] = fma2(G.c, Y0, mul2(G.ns, X1));
    X[i1] = fma2(G.c, X1, mul2(G.s, Y0));
    Y[i1] = fma2(G.c, Y1, mul2(G.ns, X0));
}

// Per-pass element address masks (applied to swizzled storage index).
template<int P>
__device__ __forceinline__ int addr_of(int base, int k) {
    if (P == 0)      return base + (k << 8);                  // immediate offsets
    else if (P == 1) return base ^ ((k << 4) | (k & 7));      // compile-time XOR mask
    else             return base ^ k;                         // compile-time XOR mask
}

// One pass, software-pipelined: loads fused with rot<8>, stores (or the fused
// measurement) fused with rot<1>.
// MODE: 0 = rot (layers 1,2), 1 = rx (layer 3), 2 = rx + fused measurement.
template<int P, int MODE>
__device__ __forceinline__ void do_pass(ulonglong2* __restrict__ st,
                                        const ulonglong2* __restrict__ g,
                                        int loadBase, int storeBase,
                                        float whigh, const float* __restrict__ wk,
                                        int wkxor, float* pacc)
{
    u64 X[16], Y[16];
    if constexpr (MODE == 0) {
        GR G0 = load_gr(g);
#pragma unroll
        for (int j = 0; j < 8; j++) {              // load pair + first rotation
            ulonglong2 a = st[addr_of<P>(loadBase, j)];
            ulonglong2 b = st[addr_of<P>(loadBase, j | 8)];
            X[j] = a.x; Y[j] = a.y; X[j | 8] = b.x; Y[j | 8] = b.y;
            rotp(G0, X, Y, j, j | 8);
        }
        GR G1 = load_gr(g + 5);
#pragma unroll
        for (int j = 0; j < 16; j++) if (!(j & 4)) rotp(G1, X, Y, j, j | 4);
        GR G2 = load_gr(g + 10);
#pragma unroll
        for (int j = 0; j < 16; j++) if (!(j & 2)) rotp(G2, X, Y, j, j | 2);
        GR G3 = load_gr(g + 15);
#pragma unroll
        for (int j = 0; j < 16; j += 2) {          // last rotation + store pair
            rotp(G3, X, Y, j, j | 1);
            ulonglong2 v0; v0.x = X[j];     v0.y = Y[j];
            st[addr_of<P>(storeBase, tau4(j))] = v0;
            ulonglong2 v1; v1.x = X[j | 1]; v1.y = Y[j | 1];
            st[addr_of<P>(storeBase, tau4(j | 1))] = v1;
        }
    } else {
        GX G0 = load_gx(g);
#pragma unroll
        for (int j = 0; j < 8; j++) {
            ulonglong2 a = st[addr_of<P>(loadBase, j)];
            ulonglong2 b = st[addr_of<P>(loadBase, j | 8)];
            X[j] = a.x; Y[j] = a.y; X[j | 8] = b.x; Y[j | 8] = b.y;
            rxp(G0, X, Y, j, j | 8);
        }
        GX G1 = load_gx(g + 5);
#pragma unroll
        for (int j = 0; j < 16; j++) if (!(j & 4)) rxp(G1, X, Y, j, j | 4);
        GX G2 = load_gx(g + 10);
#pragma unroll
        for (int j = 0; j < 16; j++) if (!(j & 2)) rxp(G2, X, Y, j, j | 2);
        GX G3 = load_gx(g + 15);
#pragma unroll
        for (int j = 0; j < 16; j += 2) {
            rxp(G3, X, Y, j, j | 1);
            if constexpr (MODE == 2) {             // fused measurement
                int i0 = tau4(j) ^ wkxor;
                float wl = whigh + wk[i0];
                u64 U = fma2(X[j], X[j], mul2(Y[j], Y[j]));
                float2 u = unpack2(U);
                pacc[0] = fmaf(u.x, wl, pacc[0]);
                pacc[1] = fmaf(u.y, wl, pacc[1]);
                int i1 = tau4(j | 1) ^ wkxor;
                wl = whigh + wk[i1];
                U = fma2(X[j | 1], X[j | 1], mul2(Y[j | 1], Y[j | 1]));
                u = unpack2(U);
                pacc[0] = fmaf(u.x, wl, pacc[0]);
                pacc[1] = fmaf(u.y, wl, pacc[1]);
            } else {
                ulonglong2 v0; v0.x = X[j];     v0.y = Y[j];
                st[addr_of<P>(storeBase, tau4(j))] = v0;
                ulonglong2 v1; v1.x = X[j | 1]; v1.y = Y[j | 1];
                st[addr_of<P>(storeBase, tau4(j | 1))] = v1;
            }
        }
    }
}

__global__ void __launch_bounds__(256, 2)
qsim3_kernel(const float* __restrict__ inputs,
             const float* __restrict__ params,
             const float* __restrict__ head_w,
             const float* __restrict__ head_b,
             float* __restrict__ out)
{
    extern __shared__ char sm[];
    ulonglong2* st   = (ulonglong2*)(sm + SM_ST);
    ulonglong2* gct  = (ulonglong2*)(sm + SM_G);
    ulonglong2* Ftab = (ulonglong2*)(sm + SM_F);
    ulonglong2* vtab = (ulonglong2*)(sm + SM_V);
    float* hw  = (float*)(sm + SM_HW);
    float* wk  = (float*)(sm + SM_WK);
    float2* red = (float2*)(sm + SM_RED);

    const int b = blockIdx.x;
    const int t = threadIdx.x;

    // ---- phase 1: gates (layers 1..3), layer-0 product vectors v, weights ----
    if (t < 36) {                      // layers 1..3, wire = t%12
        int l = 1 + t / NW, w = t % NW;
        float th = params[l * NW + w];
        float c, s; sincosf(0.5f * th, &s, &c);
        ulonglong2* g = gct + ((l - 1) * NW + w) * 5;
        u64 zc = dup2(c), zs = dup2(s);
        if (l < 3) {
            float sn = 2.f * s * c, cn = c * c - s * s;
            float A = s * sn, B = s * cn, C = c * cn, D = -c * sn;
            ulonglong2 e0; e0.x = zc;        e0.y = zs;        g[0] = e0;
            ulonglong2 e1; e1.x = dup2(-s);  e1.y = dup2(A);   g[1] = e1;
            ulonglong2 e2; e2.x = dup2(B);   e2.y = dup2(-B);  g[2] = e2;
            ulonglong2 e3; e3.x = dup2(C);   e3.y = dup2(D);   g[3] = e3;
            ulonglong2 e4; e4.x = dup2(-D);  e4.y = 0ULL;      g[4] = e4;
        } else {                        // last layer: pure RX
            ulonglong2 e0; e0.x = zc;        e0.y = zs;        g[0] = e0;
            ulonglong2 e1; e1.x = dup2(-s);  e1.y = 0ULL;      g[1] = e1;
        }
    }
    if (t < NW) {                      // layer-0 per-wire 2-vectors (both samples)
        int w = t;
        float th = params[w];
        float c0, s0; sincosf(0.5f * th, &s0, &c0);
        float cn = c0 * c0 - s0 * s0, sn = 2.f * s0 * c0;
        float v0x[2], v0y[2], v1x[2], v1y[2];
#pragma unroll
        for (int j = 0; j < 2; j++) {
            float cy, sy; sincosf(0.5f * inputs[(2 * b + j) * NW + w], &sy, &cy);
            v0x[j] = c0 * cy;  v0y[j] = -s0 * sy;
            float zx = c0 * sy, zy = -s0 * cy;           // z = -i s cy + c sy
            v1x[j] = cn * zx - sn * zy;                   // e^{i th} * z
            v1y[j] = sn * zx + cn * zy;
        }
        ulonglong2 e0; e0.x = pack2(v0x[0], v0x[1]); e0.y = pack2(v0y[0], v0y[1]);
        ulonglong2 e1; e1.x = pack2(v1x[0], v1x[1]); e1.y = pack2(v1y[0], v1y[1]);
        vtab[(w << 1) | 0] = e0;
        vtab[(w << 1) | 1] = e1;
        hw[w] = head_w[w];
    }
    if (t < 16) {                      // measurement weights for wires 8..11
        float w8 = head_w[8], w9 = head_w[9], w10 = head_w[10], w11 = head_w[11];
        wk[t] = ((t & 8) ? -w8 : w8) + ((t & 4) ? -w9 : w9)
              + ((t & 2) ? -w10 : w10) + ((t & 1) ? -w11 : w11);
    }
    __syncthreads();

    // ---- phase 2: F table (wires 0..3 staircase products, per sample-pair) ----
    if (t < 16) {
        int c0 = (t >> 3) & 1, c1 = (t >> 2) & 1, c2 = (t >> 1) & 1, c3 = t & 1;
        int b0 = c0, b1 = c1 ^ c0, b2 = c2 ^ c1, b3 = c3 ^ c2;
        ulonglong2 a = vtab[0 | b0];
        u64 PX = a.x, PY = a.y;
        int bb[3] = {b1, b2, b3};
#pragma unroll
        for (int w = 1; w <= 3; w++) {
            ulonglong2 q = vtab[(w << 1) | bb[w - 1]];
            u64 nx = fma2(PX, q.x, neg2(mul2(PY, q.y)));
            u64 ny = fma2(PX, q.y, mul2(PY, q.x));
            PX = nx; PY = ny;
        }
        ulonglong2 f; f.x = PX; f.y = PY; Ftab[t] = f;
    }

    // per-thread bases (reused across layers)
    const int baseA  = t ^ ((t >> 4) & 7);              // pass-A canonical base
    // Deferred CNOT(7,8) conjugated through the already-applied staircase:
    // Stair o C78 o Stair^-1 flips bits 3..0 iff bit 4 (Stair(8) = 0xF).
    const int tA2    = t ^ (((t >> 4) & 1) * 0xF);
    const int baseA2 = tA2 ^ ((tA2 >> 4) & 7);          // pass-A load base (L2,L3)
    const int baseB  = ((t >> 4) << 8) | (t & 15);
    const int baseBs = baseB ^ (((t >> 4) & 1) ? 0xF7 : 0);  // CNOT(3,4) fold
    const int baseC  = (t << 4) | (t & 7);
    const int wkxor  = (t & 1) ? 0xF : 0;               // CNOT(7,8) fold at measure

    // measurement weight for wires 0..7 (t bits 7..0, wire i <-> t bit 7-i)
    float whigh = 0.f;
#pragma unroll
    for (int m = 0; m < 8; m++) {
        float w = hw[7 - m];
        whigh += ((t >> m) & 1) ? -w : w;
    }
    __syncthreads();

    float pacc[2] = {0.f, 0.f};
    const ulonglong2* g1 = gct;           // layer 1
    const ulonglong2* g2 = gct + 60;      // layer 2
    const ulonglong2* g3 = gct + 120;     // layer 3 (rx)

    // ======== Layer 1, pass A: closed-form init in registers + rot + store ====
    {
        u64 X[16], Y[16];
        int u = t ^ (t >> 1);             // u bit (11-w) = b_w for wires 5..11
        ulonglong2 p5 = vtab[(5 << 1) | ((u >> 6) & 1)];
        u64 PX = p5.x, PY = p5.y;
#pragma unroll
        for (int w = 6; w <= 11; w++) {
            ulonglong2 q = vtab[(w << 1) | ((u >> (11 - w)) & 1)];
            u64 nx = fma2(PX, q.x, neg2(mul2(PY, q.y)));
            u64 ny = fma2(PX, q.y, mul2(PY, q.x));
            PX = nx; PY = ny;
        }
        int t7 = (t >> 7) & 1;
        ulonglong2 q0 = vtab[(4 << 1) | t7];
        ulonglong2 q1 = vtab[(4 << 1) | (t7 ^ 1)];
        u64 R0X = fma2(PX, q0.x, neg2(mul2(PY, q0.y)));
        u64 R0Y = fma2(PX, q0.y, mul2(PY, q0.x));
        u64 R1X = fma2(PX, q1.x, neg2(mul2(PY, q1.y)));
        u64 R1Y = fma2(PX, q1.y, mul2(PY, q1.x));
        GR G0 = load_gr(g1);
#pragma unroll
        for (int j = 0; j < 8; j++) {     // build pair (j, j|8) then rotate it
            ulonglong2 Fk0 = Ftab[j];
            u64 QX = (j & 1) ? R1X : R0X;
            u64 QY = (j & 1) ? R1Y : R0Y;
            X[j] = fma2(Fk0.x, QX, neg2(mul2(Fk0.y, QY)));
            Y[j] = fma2(Fk0.x, QY, mul2(Fk0.y, QX));
            ulonglong2 Fk1 = Ftab[j | 8];
            X[j | 8] = fma2(Fk1.x, QX, neg2(mul2(Fk1.y, QY)));
            Y[j | 8] = fma2(Fk1.x, QY, mul2(Fk1.y, QX));
            rotp(G0, X, Y, j, j | 8);
        }
        GR G1 = load_gr(g1 + 5);
#pragma unroll
        for (int j = 0; j < 16; j++) if (!(j & 4)) rotp(G1, X, Y, j, j | 4);
        GR G2 = load_gr(g1 + 10);
#pragma unroll
        for (int j = 0; j < 16; j++) if (!(j & 2)) rotp(G2, X, Y, j, j | 2);
        GR G3 = load_gr(g1 + 15);
#pragma unroll
        for (int j = 0; j < 16; j += 2) { // last rotation + store pair
            rotp(G3, X, Y, j, j | 1);
            ulonglong2 v0; v0.x = X[j];     v0.y = Y[j];
            st[baseA + (tau4(j) << 8)] = v0;
            ulonglong2 v1; v1.x = X[j | 1]; v1.y = Y[j | 1];
            st[baseA + (tau4(j | 1) << 8)] = v1;
        }
    }
    __syncthreads();

    do_pass<1, 0>(st, g1 + 20, baseB, baseBs, whigh, wk, 0, pacc); __syncthreads();
    do_pass<2, 0>(st, g1 + 40, baseC, baseC,  whigh, wk, 0, pacc); __syncthreads();

    // ======== Layer 2 ========
    do_pass<0, 0>(st, g2,      baseA2, baseA, whigh, wk, 0, pacc); __syncthreads();
    do_pass<1, 0>(st, g2 + 20, baseB,  baseBs, whigh, wk, 0, pacc); __syncthreads();
    do_pass<2, 0>(st, g2 + 40, baseC,  baseC,  whigh, wk, 0, pacc); __syncthreads();

    // ======== Layer 3 (pure RX, fused measurement in pass C) ========
    do_pass<0, 1>(st, g3,      baseA2, baseA, whigh, wk, 0, pacc); __syncthreads();
    do_pass<1, 1>(st, g3 + 20, baseB,  baseBs, whigh, wk, 0, pacc); __syncthreads();
    do_pass<2, 2>(st, g3 + 40, baseC,  baseC,  whigh, wk, wkxor, pacc);

    // ---- reduce both samples ----
    float p0 = pacc[0], p1 = pacc[1];
#pragma unroll
    for (int o = 16; o; o >>= 1) {
        p0 += __shfl_xor_sync(0xFFFFFFFFu, p0, o);
        p1 += __shfl_xor_sync(0xFFFFFFFFu, p1, o);
    }
    if ((t & 31) == 0) red[t >> 5] = make_float2(p0, p1);
    __syncthreads();
    if (t < 2) {
        float s = 0.f;
#pragma unroll
        for (int w = 0; w < 8; w++) s += (t == 0) ? red[w].x : red[w].y;
        out[2 * b + t] = s + head_b[0];
    }
}

extern "C" void kernel_launch(void* const* d_in, const int* in_sizes, int n_in,
                              void* d_out, int out_size)
{
    const float* inputs = (const float*)d_in[0];
    const float* params = (const float*)d_in[1];
    const float* head_w = (const float*)d_in[2];
    const float* head_b = (const float*)d_in[3];
    float* out = (float*)d_out;

    cudaFuncSetAttribute(qsim3_kernel, cudaFuncAttributeMaxDynamicSharedMemorySize, SMEM_BYTES);
    int B2 = out_size / 2;   // two samples per block
    qsim3_kernel<<<B2, 256, SMEM_BYTES>>>(inputs, params, head_w, head_b, out);
}

// round 7
// speedup vs baseline: 2.1661x; 1.0733x over previous
#include <cuda_runtime.h>

// QuantumRegression: 12-wire state-vector sim, two samples per block packed
// into f32x2 lanes. State = 4096 x ulonglong2 (X=f32x2, Y=f32x2) = 64KB in
// shared, storage index sw(e) = e ^ ((e>>4)&7) (conflict-free for all pass
// layouts at 16B granularity, affine-in-k addressing per pass).
//
// Circuit structure (CNOT algebra identical to the verified R5/R6 kernel):
//  - Layer 0 folded into closed-form product-state init (prefix parity).
//  - Layers 1..3: 3 passes of 4 rotated wires (0-3 / 4-7 / 8-11); boundary
//    CNOT(3,4) folded into pass-B store base, boundary CNOT(7,8) deferred
//    into next pass-A load base (conjugated: flip bits 3..0 iff bit4).
//  - NEW: RZ diagonals deferred out of the rotations. All four RZs of a
//    window collapse into one batch-shared 16-entry phase table D[m],
//    applied per amp after the pure-RX rotations, before the CNOT perm.
//    Cuts rot-pass FMA 384 -> 320 f32x2 ops and shortens dep chains.
//  - RZ global phase dropped; last layer's RZs dropped entirely (diagonal
//    before |amp|^2); last layer = pure RX. <Z>@head_w measurement fused.

typedef unsigned long long u64;

#define NW 12

// ---- packed f32x2 helpers ----
static __device__ __forceinline__ u64 pack2(float lo, float hi) {
    u64 r; asm("mov.b64 %0, {%1, %2};" : "=l"(r) : "f"(lo), "f"(hi)); return r;
}
static __device__ __forceinline__ float2 unpack2(u64 v) {
    float2 r; asm("mov.b64 {%0, %1}, %2;" : "=f"(r.x), "=f"(r.y) : "l"(v)); return r;
}
static __device__ __forceinline__ u64 dup2(float v) { return pack2(v, v); }
static __device__ __forceinline__ u64 fma2(u64 a, u64 b, u64 c) {
    u64 d; asm("fma.rn.f32x2 %0, %1, %2, %3;" : "=l"(d) : "l"(a), "l"(b), "l"(c)); return d;
}
static __device__ __forceinline__ u64 mul2(u64 a, u64 b) {
    u64 d; asm("mul.rn.f32x2 %0, %1, %2;" : "=l"(d) : "l"(a), "l"(b)); return d;
}
static __device__ __forceinline__ u64 neg2(u64 a) { return a ^ 0x8000000080000000ULL; }

// staircase CNOT permutation on 4 bits (GF2-linear)
__device__ __host__ __forceinline__ constexpr int tau4(int k) {
    int b3 = (k >> 3) & 1;
    int b2 = ((k >> 2) & 1) ^ b3;
    int b1 = ((k >> 1) & 1) ^ b2;
    int b0 = (k & 1) ^ b1;
    return (b3 << 3) | (b2 << 2) | (b1 << 1) | b0;
}

// ---- shared memory layout (bytes) ----
#define SM_ST   0        // ulonglong2 st[4096]            : 65536
#define SM_G    65536    // ulonglong2 gx[3*12] (c,s)      : 576
#define SM_D    66112    // ulonglong2 dtab[2*3*16]        : 1536  (L1,L2 diag)
#define SM_V    67648    // ulonglong2 v[12][2]            : 384
#define SM_F    68032    // ulonglong2 F[16]               : 256
#define SM_HW   68288    // float hw[12]                   : 48
#define SM_WK   68336    // float wk[16]                   : 64
#define SM_RED  68400    // float2 red[8]                  : 64
#define SMEM_BYTES 68464

// ---- RX gate bundle: one LDS.128, ns derived ----
struct GX { u64 c, s, ns; };
static __device__ __forceinline__ GX load_gx(const ulonglong2* __restrict__ g) {
    GX r; ulonglong2 p = g[0]; r.c = p.x; r.s = p.y; r.ns = neg2(p.y); return r;
}

// one pure RX rotation on pair (i0, i1)
static __device__ __forceinline__ void rxp(const GX& G, u64* X, u64* Y, int i0, int i1) {
    u64 X0 = X[i0], Y0 = Y[i0], X1 = X[i1], Y1 = Y[i1];
    X[i0] = fma2(G.c, X0, mul2(G.s, Y1));
    Y[i0] = fma2(G.c, Y0, mul2(G.ns, X1));
    X[i1] = fma2(G.c, X1, mul2(G.s, Y0));
    Y[i1] = fma2(G.c, Y1, mul2(G.ns, X0));
}

// apply window diagonal D[slot] (unit phase, batch-shared) to slot k
static __device__ __forceinline__ void diagp(const ulonglong2* __restrict__ dt,
                                             u64* X, u64* Y, int k) {
    ulonglong2 d = dt[k];
    u64 nx = fma2(d.x, X[k], neg2(mul2(d.y, Y[k])));
    u64 ny = fma2(d.x, Y[k], mul2(d.y, X[k]));
    X[k] = nx; Y[k] = ny;
}

// Per-pass element address masks (applied to swizzled storage index).
template<int P>
__device__ __forceinline__ int addr_of(int base, int k) {
    if (P == 0)      return base + (k << 8);                  // immediate offsets
    else if (P == 1) return base ^ ((k << 4) | (k & 7));      // compile-time XOR mask
    else             return base ^ k;                         // compile-time XOR mask
}

// One pass: 4 pure-RX rotations (gates g[0..3]), then per MODE:
//  MODE 0: window diagonal dt + CNOT-permuted store   (layers 1,2)
//  MODE 1: CNOT-permuted store, no diagonal           (layer 3, passes A,B)
//  MODE 2: fused measurement, no diagonal             (layer 3, pass C)
template<int P, int MODE>
__device__ __forceinline__ void do_pass(ulonglong2* __restrict__ st,
                                        const ulonglong2* __restrict__ g,
                                        const ulonglong2* __restrict__ dt,
                                        int loadBase, int storeBase,
                                        float whigh, const float* __restrict__ wk,
                                        int wkxor, float* pacc)
{
    u64 X[16], Y[16];
    GX G0 = load_gx(g);
#pragma unroll
    for (int j = 0; j < 8; j++) {              // load pair + first rotation
        ulonglong2 a = st[addr_of<P>(loadBase, j)];
        ulonglong2 b = st[addr_of<P>(loadBase, j | 8)];
        X[j] = a.x; Y[j] = a.y; X[j | 8] = b.x; Y[j | 8] = b.y;
        rxp(G0, X, Y, j, j | 8);
    }
    GX G1 = load_gx(g + 1);
#pragma unroll
    for (int j = 0; j < 16; j++) if (!(j & 4)) rxp(G1, X, Y, j, j | 4);
    GX G2 = load_gx(g + 2);
#pragma unroll
    for (int j = 0; j < 16; j++) if (!(j & 2)) rxp(G2, X, Y, j, j | 2);
    GX G3 = load_gx(g + 3);
#pragma unroll
    for (int j = 0; j < 16; j += 2) {          // last rotation + epilogue
        rxp(G3, X, Y, j, j | 1);
        if constexpr (MODE == 2) {             // fused measurement
            int i0 = tau4(j) ^ wkxor;
            float wl = whigh + wk[i0];
            u64 U = fma2(X[j], X[j], mul2(Y[j], Y[j]));
            float2 u = unpack2(U);
            pacc[0] = fmaf(u.x, wl, pacc[0]);
            pacc[1] = fmaf(u.y, wl, pacc[1]);
            int i1 = tau4(j | 1) ^ wkxor;
            wl = whigh + wk[i1];
            U = fma2(X[j | 1], X[j | 1], mul2(Y[j | 1], Y[j | 1]));
            u = unpack2(U);
            pacc[0] = fmaf(u.x, wl, pacc[0]);
            pacc[1] = fmaf(u.y, wl, pacc[1]);
        } else {
            if constexpr (MODE == 0) { diagp(dt, X, Y, j); diagp(dt, X, Y, j | 1); }
            ulonglong2 v0; v0.x = X[j];     v0.y = Y[j];
            st[addr_of<P>(storeBase, tau4(j))] = v0;
            ulonglong2 v1; v1.x = X[j | 1]; v1.y = Y[j | 1];
            st[addr_of<P>(storeBase, tau4(j | 1))] = v1;
        }
    }
}

__global__ void __launch_bounds__(256, 2)
qsim4_kernel(const float* __restrict__ inputs,
             const float* __restrict__ params,
             const float* __restrict__ head_w,
             const float* __restrict__ head_b,
             float* __restrict__ out)
{
    extern __shared__ char sm[];
    ulonglong2* st   = (ulonglong2*)(sm + SM_ST);
    ulonglong2* gx   = (ulonglong2*)(sm + SM_G);
    ulonglong2* dtab = (ulonglong2*)(sm + SM_D);
    ulonglong2* vtab = (ulonglong2*)(sm + SM_V);
    ulonglong2* Ftab = (ulonglong2*)(sm + SM_F);
    float* hw  = (float*)(sm + SM_HW);
    float* wk  = (float*)(sm + SM_WK);
    float2* red = (float2*)(sm + SM_RED);

    const int b = blockIdx.x;
    const int t = threadIdx.x;

    // ---- phase 1: RX gates (layers 1..3), diagonal tables (layers 1..2),
    //      layer-0 product vectors, measurement weights ----
    if (t < 36) {                      // RX coeffs: layer 1+t/12, wire t%12
        float th = params[12 + t];
        float c, s; sincosf(0.5f * th, &s, &c);
        ulonglong2 e; e.x = dup2(c); e.y = dup2(s);
        gx[t] = e;
    }
    if (t >= 64 && t < 160) {          // diagonal tables: D[m] = e^{i sum th_w bit_w}
        int i = t - 64;                // layer = i/48 (0->L1), pass = (i%48)/16, m = i&15
        int l = i / 48, p = (i % 48) / 16, m = i & 15;
        const float* th = params + (l + 1) * NW + 4 * p;
        float phi = 0.f;
#pragma unroll
        for (int q = 0; q < 4; q++)
            if ((m >> (3 - q)) & 1) phi += th[q];
        float cp, sp; sincosf(phi, &sp, &cp);
        ulonglong2 e; e.x = dup2(cp); e.y = dup2(sp);
        dtab[i] = e;
    }
    if (t < NW) {                      // layer-0 per-wire 2-vectors (both samples)
        int w = t;
        float th = params[w];
        float c0, s0; sincosf(0.5f * th, &s0, &c0);
        float cn = c0 * c0 - s0 * s0, sn = 2.f * s0 * c0;
        float v0x[2], v0y[2], v1x[2], v1y[2];
#pragma unroll
        for (int j = 0; j < 2; j++) {
            float cy, sy; sincosf(0.5f * inputs[(2 * b + j) * NW + w], &sy, &cy);
            v0x[j] = c0 * cy;  v0y[j] = -s0 * sy;
            float zx = c0 * sy, zy = -s0 * cy;           // z = -i s cy + c sy
            v1x[j] = cn * zx - sn * zy;                   // e^{i th} * z
            v1y[j] = sn * zx + cn * zy;
        }
        ulonglong2 e0; e0.x = pack2(v0x[0], v0x[1]); e0.y = pack2(v0y[0], v0y[1]);
        ulonglong2 e1; e1.x = pack2(v1x[0], v1x[1]); e1.y = pack2(v1y[0], v1y[1]);
        vtab[(w << 1) | 0] = e0;
        vtab[(w << 1) | 1] = e1;
        hw[w] = head_w[w];
    }
    if (t < 16) {                      // measurement weights for wires 8..11
        float w8 = head_w[8], w9 = head_w[9], w10 = head_w[10], w11 = head_w[11];
        wk[t] = ((t & 8) ? -w8 : w8) + ((t & 4) ? -w9 : w9)
              + ((t & 2) ? -w10 : w10) + ((t & 1) ? -w11 : w11);
    }
    __syncthreads();

    // ---- phase 2: F table (wires 0..3 staircase products, per sample-pair) ----
    if (t < 16) {
        int c0 = (t >> 3) & 1, c1 = (t >> 2) & 1, c2 = (t >> 1) & 1, c3 = t & 1;
        int b0 = c0, b1 = c1 ^ c0, b2 = c2 ^ c1, b3 = c3 ^ c2;
        ulonglong2 a = vtab[0 | b0];
        u64 PX = a.x, PY = a.y;
        int bb[3] = {b1, b2, b3};
#pragma unroll
        for (int w = 1; w <= 3; w++) {
            ulonglong2 q = vtab[(w << 1) | bb[w - 1]];
            u64 nx = fma2(PX, q.x, neg2(mul2(PY, q.y)));
            u64 ny = fma2(PX, q.y, mul2(PY, q.x));
            PX = nx; PY = ny;
        }
        ulonglong2 f; f.x = PX; f.y = PY; Ftab[t] = f;
    }

    // per-thread bases (reused across layers)
    const int baseA  = t ^ ((t >> 4) & 7);              // pass-A canonical base
    // Deferred CNOT(7,8) conjugated through the already-applied staircase:
    // flips bits 3..0 iff bit 4 (Stair(8) = 0xF).
    const int tA2    = t ^ (((t >> 4) & 1) * 0xF);
    const int baseA2 = tA2 ^ ((tA2 >> 4) & 7);          // pass-A load base (L2,L3)
    const int baseB  = ((t >> 4) << 8) | (t & 15);
    const int baseBs = baseB ^ (((t >> 4) & 1) ? 0xF7 : 0);  // CNOT(3,4) fold
    const int baseC  = (t << 4) | (t & 7);
    const int wkxor  = (t & 1) ? 0xF : 0;               // CNOT(7,8) fold at measure

    // measurement weight for wires 0..7 (t bits 7..0, wire i <-> t bit 7-i)
    float whigh = 0.f;
#pragma unroll
    for (int m = 0; m < 8; m++) {
        float w = hw[7 - m];
        whigh += ((t >> m) & 1) ? -w : w;
    }
    __syncthreads();

    float pacc[2] = {0.f, 0.f};
    const ulonglong2* g1 = gx;            // layer 1 (12 gates)
    const ulonglong2* g2 = gx + 12;       // layer 2
    const ulonglong2* g3 = gx + 24;       // layer 3
    const ulonglong2* d1 = dtab;          // layer-1 diagonals (3 passes x 16)
    const ulonglong2* d2 = dtab + 48;     // layer-2 diagonals

    // ======== Layer 1, pass A: closed-form init + rx chain + diag + store ====
    {
        u64 X[16], Y[16];
        int u = t ^ (t >> 1);             // u bit (11-w) = b_w for wires 5..11
        ulonglong2 p5 = vtab[(5 << 1) | ((u >> 6) & 1)];
        u64 PX = p5.x, PY = p5.y;
#pragma unroll
        for (int w = 6; w <= 11; w++) {
            ulonglong2 q = vtab[(w << 1) | ((u >> (11 - w)) & 1)];
            u64 nx = fma2(PX, q.x, neg2(mul2(PY, q.y)));
            u64 ny = fma2(PX, q.y, mul2(PY, q.x));
            PX = nx; PY = ny;
        }
        int t7 = (t >> 7) & 1;
        ulonglong2 q0 = vtab[(4 << 1) | t7];
        ulonglong2 q1 = vtab[(4 << 1) | (t7 ^ 1)];
        u64 R0X = fma2(PX, q0.x, neg2(mul2(PY, q0.y)));
        u64 R0Y = fma2(PX, q0.y, mul2(PY, q0.x));
        u64 R1X = fma2(PX, q1.x, neg2(mul2(PY, q1.y)));
        u64 R1Y = fma2(PX, q1.y, mul2(PY, q1.x));
        GX G0 = load_gx(g1);
#pragma unroll
        for (int j = 0; j < 8; j++) {     // build pair (j, j|8) then rotate it
            ulonglong2 Fk0 = Ftab[j];
            u64 QX = (j & 1) ? R1X : R0X;
            u64 QY = (j & 1) ? R1Y : R0Y;
            X[j] = fma2(Fk0.x, QX, neg2(mul2(Fk0.y, QY)));
            Y[j] = fma2(Fk0.x, QY, mul2(Fk0.y, QX));
            ulonglong2 Fk1 = Ftab[j | 8];
            X[j | 8] = fma2(Fk1.x, QX, neg2(mul2(Fk1.y, QY)));
            Y[j | 8] = fma2(Fk1.x, QY, mul2(Fk1.y, QX));
            rxp(G0, X, Y, j, j | 8);
        }
        GX G1 = load_gx(g1 + 1);
#pragma unroll
        for (int j = 0; j < 16; j++) if (!(j & 4)) rxp(G1, X, Y, j, j | 4);
        GX G2 = load_gx(g1 + 2);
#pragma unroll
        for (int j = 0; j < 16; j++) if (!(j & 2)) rxp(G2, X, Y, j, j | 2);
        GX G3 = load_gx(g1 + 3);
#pragma unroll
        for (int j = 0; j < 16; j += 2) { // last rotation + diagonal + store
            rxp(G3, X, Y, j, j | 1);
            diagp(d1, X, Y, j); diagp(d1, X, Y, j | 1);
            ulonglong2 v0; v0.x = X[j];     v0.y = Y[j];
            st[baseA + (tau4(j) << 8)] = v0;
            ulonglong2 v1; v1.x = X[j | 1]; v1.y = Y[j | 1];
            st[baseA + (tau4(j | 1) << 8)] = v1;
        }
    }
    __syncthreads();

    do_pass<1, 0>(st, g1 + 4, d1 + 16, baseB, baseBs, whigh, wk, 0, pacc); __syncthreads();
    do_pass<2, 0>(st, g1 + 8, d1 + 32, baseC, baseC,  whigh, wk, 0, pacc); __syncthreads();

    // ======== Layer 2 ========
    do_pass<0, 0>(st, g2,     d2,      baseA2, baseA,  whigh, wk, 0, pacc); __syncthreads();
    do_pass<1, 0>(st, g2 + 4, d2 + 16, baseB,  baseBs, whigh, wk, 0, pacc); __syncthreads();
    do_pass<2, 0>(st, g2 + 8, d2 + 32, baseC,  baseC,  whigh, wk, 0, pacc); __syncthreads();

    // ======== Layer 3 (pure RX, fused measurement in pass C) ========
    do_pass<0, 1>(st, g3,     nullptr, baseA2, baseA,  whigh, wk, 0, pacc); __syncthreads();
    do_pass<1, 1>(st, g3 + 4, nullptr, baseB,  baseBs, whigh, wk, 0, pacc); __syncthreads();
    do_pass<2, 2>(st, g3 + 8, nullptr, baseC,  baseC,  whigh, wk, wkxor, pacc);

    // ---- reduce both samples ----
    float p0 = pacc[0], p1 = pacc[1];
#pragma unroll
    for (int o = 16; o; o >>= 1) {
        p0 += __shfl_xor_sync(0xFFFFFFFFu, p0, o);
        p1 += __shfl_xor_sync(0xFFFFFFFFu, p1, o);
    }
    if ((t & 31) == 0) red[t >> 5] = make_float2(p0, p1);
    __syncthreads();
    if (t < 2) {
        float s = 0.f;
#pragma unroll
        for (int w = 0; w < 8; w++) s += (t == 0) ? red[w].x : red[w].y;
        out[2 * b + t] = s + head_b[0];
    }
}

extern "C" void kernel_launch(void* const* d_in, const int* in_sizes, int n_in,
                              void* d_out, int out_size)
{
    const float* inputs = (const float*)d_in[0];
    const float* params = (const float*)d_in[1];
    const float* head_w = (const float*)d_in[2];
    const float* head_b = (const float*)d_in[3];
    float* out = (float*)d_out;

    cudaFuncSetAttribute(qsim4_kernel, cudaFuncAttributeMaxDynamicSharedMemorySize, SMEM_BYTES);
    int B2 = out_size / 2;   // two samples per block
    qsim4_kernel<<<B2, 256, SMEM_BYTES>>>(inputs, params, head_w, head_b, out);
}